// round 1
// baseline (speedup 1.0000x reference)
#include <cuda_runtime.h>
#include <cstdint>

#define NPT 8192          // points per side
#define DIM 256           // feature dim
#define LOG2E  1.4426950408889634f
#define LN2    0.6931471805599453f
#define LOGN   9.0109133472f          // log(8192)
#define KS     (1.4426950408889634f / 64.0f)   // log2(e)/64 : dequant*log2e fused

// ---------------- device scratch (allowed: __device__ globals) ----------------
__device__ short  gC [(size_t)NPT * NPT];   // q = round(128 * x_i . y_j), row-major in i
__device__ short  gCT[(size_t)NPT * NPT];   // transposed copy, row-major in j
__device__ float  gA[NPT], gB[NPT];         // squared norms
__device__ float  gU[NPT], gV[NPT], gS[NPT];

// ---------------- helpers ----------------
__device__ __forceinline__ float ex2(float x) {
    float r; asm("ex2.approx.ftz.f32 %0, %1;" : "=f"(r) : "f"(x)); return r;
}

// online log-sum-exp update in base-2 domain: exactly one EX2 per element
#define ONUPD(m, s, z) do {                       \
    float _d = (z) - (m);                         \
    float _e = ex2(-fabsf(_d));                   \
    if (_d > 0.0f) { (s) = fmaf((s), _e, 1.0f); (m) = (z); } \
    else           { (s) += _e; }                 \
} while (0)

// ---------------- squared norms ----------------
__global__ __launch_bounds__(256) void norms_kernel(const float* __restrict__ X, int which) {
    int warp = threadIdx.x >> 5, lane = threadIdx.x & 31;
    int row  = blockIdx.x * 8 + warp;
    const float4* xp = (const float4*)(X + (size_t)row * DIM);
    float ss = 0.0f;
    #pragma unroll
    for (int c = lane; c < DIM / 4; c += 32) {
        float4 t = xp[c];
        ss += t.x * t.x + t.y * t.y + t.z * t.z + t.w * t.w;
    }
    #pragma unroll
    for (int off = 16; off; off >>= 1)
        ss += __shfl_xor_sync(0xffffffffu, ss, off);
    if (lane == 0) { if (which) gB[row] = ss; else gA[row] = ss; }
}

__global__ void init_kernel() {
    int j = blockIdx.x * 256 + threadIdx.x;
    gV[j] = -gB[j];
    gU[j] = -gA[j];
}

// ---------------- GEMM: q = round(128 * X Y^T), writes C and C^T ----------------
#define BM 128
#define BN 128
#define BK 16

__device__ __forceinline__ unsigned pack2(int a, int b) {
    return (unsigned)(unsigned short)(short)a | ((unsigned)(unsigned short)(short)b << 16);
}

__global__ __launch_bounds__(256) void gemm_q_kernel(const float* __restrict__ X,
                                                     const float* __restrict__ Y) {
    __shared__ float As[BK][BM + 4];
    __shared__ float Bs[BK][BN + 4];
    int tid = threadIdx.x;
    int tx = tid & 15, ty = tid >> 4;
    int bi = blockIdx.y * BM, bj = blockIdx.x * BN;

    float acc[8][8];
    #pragma unroll
    for (int r = 0; r < 8; ++r)
        #pragma unroll
        for (int c = 0; c < 8; ++c) acc[r][c] = 0.0f;

    for (int k0 = 0; k0 < DIM; k0 += BK) {
        #pragma unroll
        for (int q = 0; q < 2; ++q) {
            int idx = tid + q * 256;        // 0..511
            int row = idx >> 2;             // 0..127
            int kf  = (idx & 3) << 2;       // 0,4,8,12
            float4 av = *(const float4*)&X[(size_t)(bi + row) * DIM + k0 + kf];
            As[kf + 0][row] = av.x; As[kf + 1][row] = av.y;
            As[kf + 2][row] = av.z; As[kf + 3][row] = av.w;
            float4 bv = *(const float4*)&Y[(size_t)(bj + row) * DIM + k0 + kf];
            Bs[kf + 0][row] = bv.x; Bs[kf + 1][row] = bv.y;
            Bs[kf + 2][row] = bv.z; Bs[kf + 3][row] = bv.w;
        }
        __syncthreads();
        #pragma unroll
        for (int kk = 0; kk < BK; ++kk) {
            float ra[8], rb[8];
            *(float4*)&ra[0] = *(const float4*)&As[kk][ty * 8];
            *(float4*)&ra[4] = *(const float4*)&As[kk][ty * 8 + 4];
            *(float4*)&rb[0] = *(const float4*)&Bs[kk][tx * 8];
            *(float4*)&rb[4] = *(const float4*)&Bs[kk][tx * 8 + 4];
            #pragma unroll
            for (int r = 0; r < 8; ++r)
                #pragma unroll
                for (int c = 0; c < 8; ++c)
                    acc[r][c] = fmaf(ra[r], rb[c], acc[r][c]);
        }
        __syncthreads();
    }

    int row_i = bi + ty * 8, col_j = bj + tx * 8;
    int qv[8][8];
    #pragma unroll
    for (int r = 0; r < 8; ++r)
        #pragma unroll
        for (int c = 0; c < 8; ++c) {
            int qi = __float2int_rn(acc[r][c] * 128.0f);
            qi = max(-32767, min(32767, qi));
            qv[r][c] = qi;
        }
    // C rows (coalesced)
    #pragma unroll
    for (int r = 0; r < 8; ++r) {
        uint4 pk;
        pk.x = pack2(qv[r][0], qv[r][1]); pk.y = pack2(qv[r][2], qv[r][3]);
        pk.z = pack2(qv[r][4], qv[r][5]); pk.w = pack2(qv[r][6], qv[r][7]);
        *(uint4*)&gC[(size_t)(row_i + r) * NPT + col_j] = pk;
    }
    // C^T rows
    #pragma unroll
    for (int c = 0; c < 8; ++c) {
        uint4 pk;
        pk.x = pack2(qv[0][c], qv[1][c]); pk.y = pack2(qv[2][c], qv[3][c]);
        pk.z = pack2(qv[4][c], qv[5][c]); pk.w = pack2(qv[6][c], qv[7][c]);
        *(uint4*)&gCT[(size_t)(col_j + c) * NPT + row_i] = pk;
    }
}

// ---------------- row logsumexp pass ----------------
// out[i] = LOGN - ln2 * log2( sum_j 2^( w2[j] + q[i][j]*KS ) )
// mode 0: mat=gC , w=gV, out=gU   (u-update)
// mode 1: mat=gCT, w=gU, out=gV   (v-update)
// mode 2: mat=gC , w=gV, out=gS   (final row sums)
#define ROWS_PER_CTA 16

__global__ __launch_bounds__(256) void row_lse_kernel(int mode) {
    __shared__ float w2[NPT];
    const short* __restrict__ Cq = (mode == 1) ? gCT : gC;
    const float* __restrict__ w  = (mode == 1) ? gU  : gV;
    float* __restrict__ out = (mode == 0) ? gU : ((mode == 1) ? gV : gS);

    int tid = threadIdx.x;
    const float4* w4 = (const float4*)w;
    for (int idx = tid; idx < NPT / 4; idx += 256) {
        float4 t = w4[idx];
        t.x *= LOG2E; t.y *= LOG2E; t.z *= LOG2E; t.w *= LOG2E;
        ((float4*)w2)[idx] = t;
    }
    __syncthreads();

    int warp = tid >> 5, lane = tid & 31;
    int r0 = blockIdx.x * ROWS_PER_CTA;

    for (int rr = warp; rr < ROWS_PER_CTA; rr += 8) {
        int i = r0 + rr;
        const short4* rowp = (const short4*)(Cq + (size_t)i * NPT);
        float m0 = -__int_as_float(0x7f800000), s0 = 0.0f;
        float m1 = -__int_as_float(0x7f800000), s1 = 0.0f;
        #pragma unroll 4
        for (int c = 0; c < NPT / 128; ++c) {          // 64 steps of 4 elems/lane
            int v4i = c * 32 + lane;
            short4 q = rowp[v4i];
            float4 vv = *(const float4*)(w2 + (size_t)v4i * 4);
            float z0 = fmaf((float)q.x, KS, vv.x);
            float z1 = fmaf((float)q.y, KS, vv.y);
            float z2 = fmaf((float)q.z, KS, vv.z);
            float z3 = fmaf((float)q.w, KS, vv.w);
            ONUPD(m0, s0, z0); ONUPD(m1, s1, z1);
            ONUPD(m0, s0, z2); ONUPD(m1, s1, z3);
        }
        // merge the two per-lane accumulators
        float m = fmaxf(m0, m1);
        float s = s0 * ex2(m0 - m) + s1 * ex2(m1 - m);
        // warp reduction of (m, s)
        #pragma unroll
        for (int off = 16; off; off >>= 1) {
            float mo = __shfl_xor_sync(0xffffffffu, m, off);
            float so = __shfl_xor_sync(0xffffffffu, s, off);
            float mn = fmaxf(m, mo);
            s = s * ex2(m - mn) + so * ex2(mo - mn);
            m = mn;
        }
        if (lane == 0) out[i] = LOGN - LN2 * (m + log2f(s));
    }
}

// ---------------- final value reduction ----------------
// t_i = LOGN - S_i ;  r_i = exp(u_i - 2*LOGN + t_i) = exp(u_i - LOGN - S_i)
// value = sum_i (a_i + u_i) * r_i + (1/N) * sum_j (b_j + v_j);  out = sqrt(value)
__global__ __launch_bounds__(256) void final_kernel(float* __restrict__ out) {
    __shared__ float red[256];
    int tid = threadIdx.x;
    float acc = 0.0f;
    for (int i = tid; i < NPT; i += 256) {
        float fi = gA[i] + gU[i];
        float ri = expf(gU[i] - LOGN - gS[i]);
        float gj = gB[i] + gV[i];
        acc += fi * ri + gj * (1.0f / NPT);
    }
    red[tid] = acc;
    __syncthreads();
    #pragma unroll
    for (int st = 128; st; st >>= 1) {
        if (tid < st) red[tid] += red[tid + st];
        __syncthreads();
    }
    if (tid == 0) out[0] = sqrtf(red[0]);
}

// ---------------- launch ----------------
extern "C" void kernel_launch(void* const* d_in, const int* in_sizes, int n_in,
                              void* d_out, int out_size) {
    const float* X = (const float*)d_in[0];   // source [8192, 256]
    const float* Y = (const float*)d_in[1];   // target [8192, 256]
    float* out = (float*)d_out;

    norms_kernel<<<NPT / 8, 256>>>(X, 0);
    norms_kernel<<<NPT / 8, 256>>>(Y, 1);
    init_kernel<<<NPT / 256, 256>>>();

    dim3 gg(NPT / BN, NPT / BM);
    gemm_q_kernel<<<gg, 256>>>(X, Y);

    for (int it = 0; it < 50; ++it) {
        row_lse_kernel<<<NPT / ROWS_PER_CTA, 256>>>(0);  // u <- v (rows of C)
        row_lse_kernel<<<NPT / ROWS_PER_CTA, 256>>>(1);  // v <- u (rows of C^T)
    }
    row_lse_kernel<<<NPT / ROWS_PER_CTA, 256>>>(2);      // S_i with final v
    final_kernel<<<1, 256>>>(out);
}